// round 13
// baseline (speedup 1.0000x reference)
#include <cuda_runtime.h>
#include <cuda_bf16.h>

// ChamferDist via x-binned pruned NN search — warp-autonomous version.
// Each warp owns 64 x-contiguous (sorted) queries, expands bins outward from
// its home bin, and stops a direction when the x-gap exceeds the warp's max
// NN radius. All reductions are warp shuffles; the hot path has NO
// __syncthreads and NO shared-memory staging (refs are broadcast __ldg).
// Exact: min over a set is order-invariant; pruning bound is conservative.

#define NB 8
#define NP 4096
#define BINS 128
#define XLO (-4.5f)
#define XW (9.0f / BINS)
#define INVW ((float)BINS / 9.0f)

#define TB 512              // bucket threads
#define TM 128              // main threads (4 warps)
#define QW 64               // queries per warp (2 per thread)
#define TILE_P (4 * QW)     // 256 queries per block
#define PT (NP / TILE_P)    // 16 tiles per (dir,batch)
#define NBLK (2 * NB * PT)  // 256 main blocks

#define F_INF __int_as_float(0x7F800000)

// Scratch (allocations forbidden).
__device__ float4 g_q[2 * NB * NP];               // (x, y, z, |p|^2), bucketed
__device__ float4 g_r[2 * NB * NP];               // (-2x, -2y, -2z, |p|^2), bucketed
__device__ int    g_boff[2 * NB * (BINS + 1)];    // bin start offsets
__device__ float  g_part[NBLK];                   // per-block sqrt-sums
__device__ int    g_ctr;                          // done-block counter

__device__ __forceinline__ int bin_of(float x) {
    int b = (int)floorf((x - XLO) * INVW);
    return min(BINS - 1, max(0, b));
}

// One block per (array,batch). arr 0 = tar, arr 1 = src.
__global__ __launch_bounds__(TB) void cd_bucket(const float* __restrict__ tar,
                                                const float* __restrict__ src) {
    __shared__ int scount[BINS];
    __shared__ int soff[BINS + 1];

    int arr = blockIdx.x >> 3, batch = blockIdx.x & 7;
    if (blockIdx.x == 0 && threadIdx.x == 0) g_ctr = 0;  // reset per replay
    const float* in = (arr == 0 ? tar : src) + (size_t)batch * NP * 3;
    int tid = threadIdx.x, lane = tid & 31;

    for (int b = tid; b < BINS; b += TB) scount[b] = 0;
    __syncthreads();

    // pass 1: counts (warp-aggregated atomics)
    for (int i = tid; i < NP; i += TB) {
        int bin = bin_of(in[3 * i]);
        unsigned peers = __match_any_sync(0xffffffffu, bin);
        int leader = __ffs(peers) - 1;
        if (lane == leader) atomicAdd(&scount[bin], __popc(peers));
    }
    __syncthreads();

    if (tid == 0) {
        int acc = 0;
        for (int b = 0; b < BINS; ++b) { soff[b] = acc; acc += scount[b]; }
        soff[BINS] = acc;
    }
    __syncthreads();

    int obase = (arr * NB + batch) * (BINS + 1);
    for (int b = tid; b <= BINS; b += TB) g_boff[obase + b] = soff[b];
    for (int b = tid; b < BINS; b += TB) scount[b] = soff[b];  // running offsets
    __syncthreads();

    // pass 2: scatter (order within bin irrelevant: min/mean are invariant)
    int pbase = (arr * NB + batch) * NP;
    for (int i = tid; i < NP; i += TB) {
        float x = in[3 * i], y = in[3 * i + 1], z = in[3 * i + 2];
        int bin = bin_of(x);
        unsigned peers = __match_any_sync(0xffffffffu, bin);
        int leader = __ffs(peers) - 1;
        int rank = __popc(peers & ((1u << lane) - 1u));
        int base;
        if (lane == leader) base = atomicAdd(&scount[bin], __popc(peers));
        base = __shfl_sync(0xffffffffu, base, leader);
        int slot = pbase + base + rank;
        float n2 = fmaf(x, x, fmaf(y, y, z * z));
        g_q[slot] = make_float4(x, y, z, n2);
        g_r[slot] = make_float4(-2.0f * x, -2.0f * y, -2.0f * z, n2);
    }
}

// dir 0: queries = tar (arr0), refs = src (arr1) -> complete
// dir 1: queries = src (arr1), refs = tar (arr0) -> accuracy
__global__ __launch_bounds__(TM) void cd_main(float* __restrict__ out) {
    __shared__ float sred[4];
    __shared__ int   s_last;

    int bid   = blockIdx.x;
    int tile  = bid % PT;
    int batch = (bid / PT) % NB;
    int dir   = bid / (PT * NB);
    int qarr  = dir;
    int rarr  = 1 - dir;

    int tid = threadIdx.x, lane = tid & 31, wid = tid >> 5;

    // This warp's 64 queries (2 per thread, stride 32).
    const float4* qb = g_q + (qarr * NB + batch) * NP + tile * TILE_P + wid * QW;
    float4 q0 = __ldg(&qb[lane]);
    float4 q1 = __ldg(&qb[lane + 32]);
    float qn0 = q0.w, qn1 = q1.w;
    float m0 = F_INF, m1 = F_INF;

    // Warp x-range (shuffle reduce; warp-uniform result).
    float xl = fminf(q0.x, q1.x), xh = fmaxf(q0.x, q1.x);
#pragma unroll
    for (int o = 16; o; o >>= 1) {
        xl = fminf(xl, __shfl_xor_sync(0xffffffffu, xl, o));
        xh = fmaxf(xh, __shfl_xor_sync(0xffffffffu, xh, o));
    }

    const float4* rf = g_r + (rarr * NB + batch) * NP;
    const int* boff = g_boff + (rarr * NB + batch) * (BINS + 1);

    // Process one bin: refs broadcast via uniform __ldg; no smem, no barriers.
#define PROCESS_BIN(b)                                                        \
    do {                                                                      \
        int _j0 = __ldg(&boff[(b)]);                                          \
        int _j1 = __ldg(&boff[(b) + 1]);                                      \
        _Pragma("unroll 4")                                                   \
        for (int _j = _j0; _j < _j1; ++_j) {                                  \
            float4 s = __ldg(&rf[_j]);                                        \
            float d0 = fmaf(q0.x, s.x, fmaf(q0.y, s.y, fmaf(q0.z, s.z, s.w)));\
            float d1 = fmaf(q1.x, s.x, fmaf(q1.y, s.y, fmaf(q1.z, s.z, s.w)));\
            m0 = fminf(m0, d0);                                               \
            m1 = fminf(m1, d1);                                               \
        }                                                                     \
    } while (0)

    int hm = bin_of(0.5f * (xl + xh));
    PROCESS_BIN(hm);

    int l = hm - 1, r = hm + 1;
    bool goL = (l >= 0), goR = (r < BINS);
    while (goL || goR) {
        // Warp max NN radius^2 (inf until something processed).
        float r2 = fmaxf(fmaxf(m0 + qn0, m1 + qn1), 0.0f);
#pragma unroll
        for (int o = 16; o; o >>= 1)
            r2 = fmaxf(r2, __shfl_xor_sync(0xffffffffu, r2, o));

        if (goL) {
            float dx = xl - (XLO + (float)(l + 1) * XW);  // gap to bin l upper edge
            if (dx > 0.0f && dx * dx > r2) goL = false;
            else { PROCESS_BIN(l); --l; goL = (l >= 0); }
        }
        if (goR) {
            float dx = (XLO + (float)r * XW) - xh;        // gap to bin r lower edge
            if (dx > 0.0f && dx * dx > r2) goR = false;
            else { PROCESS_BIN(r); ++r; goR = (r < BINS); }
        }
    }
#undef PROCESS_BIN

    // Finalize: sqrt(min d^2) for both queries, warp sum, block sum.
    float s = sqrtf(fmaxf(m0 + qn0, 0.0f)) + sqrtf(fmaxf(m1 + qn1, 0.0f));
#pragma unroll
    for (int o = 16; o; o >>= 1) s += __shfl_xor_sync(0xffffffffu, s, o);
    if (lane == 0) sred[wid] = s;
    __syncthreads();

    // Publish partial; last block does the deterministic fixed-order finish.
    if (tid == 0) {
        g_part[bid] = sred[0] + sred[1] + sred[2] + sred[3];
        __threadfence();
        int old = atomicAdd(&g_ctr, 1);
        s_last = (old == NBLK - 1);
    }
    __syncthreads();
    if (s_last) {
        __shared__ float bsum[16];
        if (tid < 16) {
            float acc = 0.0f;
#pragma unroll
            for (int i = 0; i < PT; ++i) acc += g_part[tid * PT + i];
            bsum[tid] = acc;
        }
        __syncthreads();
        if (tid == 0) {
            float comp = 0.0f, acc = 0.0f;
#pragma unroll
            for (int b = 0; b < NB; ++b) { comp += bsum[b]; acc += bsum[8 + b]; }
            comp *= (1.0f / (float)(NB * NP));
            acc  *= (1.0f / (float)(NB * NP));
            out[0] = acc;
            out[1] = comp;
            out[2] = 0.5f * (acc + comp);
        }
    }
}

extern "C" void kernel_launch(void* const* d_in, const int* in_sizes, int n_in,
                              void* d_out, int out_size) {
    const float* tar = (const float*)d_in[0];
    const float* src = (const float*)d_in[1];
    float* out = (float*)d_out;

    cd_bucket<<<16, TB>>>(tar, src);
    cd_main<<<NBLK, TM>>>(out);
}